// round 12
// baseline (speedup 1.0000x reference)
#include <cuda_runtime.h>
#include <cuda_bf16.h>
#include <math_constants.h>
#include <math.h>

#define CDIM     64
#define NCODES   1024
#define KTOT     2048
#define BATCH    32
#define N_VEC    (BATCH * KTOT)          // 65536
#define Z_ELEMS  (BATCH * CDIM * KTOT)   // 4194304
#define MTILE    128                     // vectors per CTA
#define NKS      8                       // k16 steps (K=128: A=[zh|zl], B=[eh|eh])
#define CHUNKC   64                      // codes per chunk
#define NCHUNKS  (NCODES / CHUNKC)       // 16
#define NTHREADS 512
#define NGRID    512
#define APITCH   136                     // halves per A row (128 + 8 pad)
#define BPITCH   72                      // halves per B row (64 eh + 8 pad)

// smem layout (bytes)
#define A_B      0                        // A halves 128x136x2 = 34816
#define B0_B     34816                    // B chunk buf0 9216
#define B1_B     44032                    // B chunk buf1 9216
#define ZS_B     53248                    // persistent fp32 z tile 64x128 = 32768
#define EES0_B   86016                    // 64 floats
#define EES1_B   86272                    // 64 floats
#define ZZS_B    86528                    // 128 floats
#define SLS_B    87040                    // 16 doubles
#define FLG_B    87168                    // flag int (+pad)
#define RED_B    87232                    // finalize: 512 f + 512 d = 6144
#define SMEM_BYTES 93376

// post-mainloop reuse inside [0, ZS_B):
#define MGD_B    0                        // float [12][128] = 6144
#define MGI_B    6144                     // int   [12][128] = 6144
#define CAND_B   12288                    // int   [4][128]  = 2048
#define RFND_B   14336                    // float [4][128]  = 2048
#define RFNI_B   16384                    // int   [4][128]  = 2048
#define STQ_B    18432                    // 32768 -> ends 51200 < ZS_B

#define B_CHUNK_U4  576                  // 9216 / 16

__device__ float  g_ee[NCODES];
__device__ int    g_hist[NCODES];
__device__ double g_loss_part[NGRID];
__device__ int    g_count = 0;
__device__ __align__(16) unsigned short g_bh[NCODES * BPITCH];   // [eh] codebook

// ---------------------------------------------------------------------------
__device__ __forceinline__ unsigned smem_u32(const void* p) {
    unsigned a;
    asm("{ .reg .u64 t; cvta.to.shared.u64 t, %1; cvt.u32.u64 %0, t; }"
        : "=r"(a) : "l"(p));
    return a;
}
__device__ __forceinline__ void ldsm4(unsigned& r0, unsigned& r1, unsigned& r2,
                                      unsigned& r3, unsigned addr) {
    asm volatile("ldmatrix.sync.aligned.m8n8.x4.shared.b16 {%0,%1,%2,%3}, [%4];"
                 : "=r"(r0), "=r"(r1), "=r"(r2), "=r"(r3) : "r"(addr));
}
__device__ __forceinline__ void mma16816(float* c, unsigned a0, unsigned a1,
                                         unsigned a2, unsigned a3,
                                         unsigned b0, unsigned b1) {
    asm volatile(
        "mma.sync.aligned.m16n8k16.row.col.f32.bf16.bf16.f32 "
        "{%0,%1,%2,%3}, {%4,%5,%6,%7}, {%8,%9}, {%0,%1,%2,%3};"
        : "+f"(c[0]), "+f"(c[1]), "+f"(c[2]), "+f"(c[3])
        : "r"(a0), "r"(a1), "r"(a2), "r"(a3), "r"(b0), "r"(b1));
}
__device__ __forceinline__ void cpa16(unsigned dst, const void* src) {
    asm volatile("cp.async.cg.shared.global [%0], [%1], 16;"
                 :: "r"(dst), "l"(src));
}
__device__ __forceinline__ void cpa4(unsigned dst, const void* src) {
    asm volatile("cp.async.ca.shared.global [%0], [%1], 4;"
                 :: "r"(dst), "l"(src));
}
__device__ __forceinline__ void cpa_commit() {
    asm volatile("cp.async.commit_group;" ::: "memory");
}
template <int N>
__device__ __forceinline__ void cpa_wait() {
    asm volatile("cp.async.wait_group %0;" :: "n"(N) : "memory");
}
__device__ __forceinline__ bool better(float da, int ia, float db, int ib) {
    return da < db || (da == db && ia < ib);
}

// ---------------------------------------------------------------------------
// prep: code norms (ascending-c), [eh] codebook image, zero hist
// ---------------------------------------------------------------------------
__global__ void vq_prep(const float* __restrict__ cb) {
    int j = blockIdx.x * blockDim.x + threadIdx.x;
    if (j >= NCODES) return;
    const float4* row4 = (const float4*)(cb + j * CDIM);
    float r[CDIM];
#pragma unroll
    for (int q = 0; q < CDIM / 4; ++q) {
        float4 v = __ldg(&row4[q]);
        r[q * 4 + 0] = v.x; r[q * 4 + 1] = v.y;
        r[q * 4 + 2] = v.z; r[q * 4 + 3] = v.w;
    }
    unsigned short* img = g_bh + j * BPITCH;
    float s = 0.f;
#pragma unroll
    for (int c = 0; c < CDIM; ++c) {
        float e = r[c];
        s = __fadd_rn(s, __fmul_rn(e, e));
        img[c] = __bfloat16_as_ushort(__float2bfloat16(e));
    }
#pragma unroll
    for (int c = CDIM; c < BPITCH; ++c) img[c] = 0;
    g_ee[j]   = s;
    g_hist[j] = 0;
}

// ---------------------------------------------------------------------------
// main: HMMA z.eh screen (top-3/thread), 12->4 candidate exact refine,
//       2 CTAs/SM, fused last-CTA finalize.  grid=512, block=512.
// ---------------------------------------------------------------------------
__global__ __launch_bounds__(NTHREADS, 2)
void vq_main(const float* __restrict__ z_e, const float* __restrict__ cb,
             float* __restrict__ out) {
    extern __shared__ char sm[];
    float*  zs  = (float*)(sm + ZS_B);      // persistent [c][v] 64x128
    float*  zzs = (float*)(sm + ZZS_B);
    double* sls = (double*)(sm + SLS_B);
    int*    flg = (int*)(sm + FLG_B);
    const unsigned smem_base = smem_u32(sm);

    const int tid  = threadIdx.x;
    const int lane = tid & 31;
    const int w    = tid >> 5;
    const int rg   = w & 3;                 // rows 32rg..32rg+31
    const int cg   = w >> 2;                // codes 16cg..16cg+15
    const int b    = blockIdx.x >> 4;
    const int k0v  = (blockIdx.x & 15) * MTILE;

    // --- kick off B chunk 0 prefetch immediately ---
    {
        const uint4* src = (const uint4*)g_bh;
#pragma unroll
        for (int i = 0; i < 2; ++i) {
            int idx = tid + i * NTHREADS;
            if (idx < B_CHUNK_U4) cpa16(smem_base + B0_B + idx * 16, src + idx);
        }
        if (tid < CHUNKC) cpa4(smem_base + EES0_B + tid * 4, &g_ee[tid]);
        cpa_commit();
    }

    // --- load z tile fp32 (persistent, coalesced float4) ---
    const float* zbase = z_e + ((size_t)b * CDIM) * KTOT + k0v;
#pragma unroll
    for (int i = 0; i < 4; ++i) {
        int idx4 = tid + i * NTHREADS;       // 0..2047
        int c = idx4 >> 5, v4 = idx4 & 31;
        *(float4*)&zs[c * MTILE + v4 * 4] =
            *(const float4*)(zbase + (size_t)c * KTOT + v4 * 4);
    }
    __syncthreads();

    // --- per-vector norm (ascending-c) + A=[zh|zl] image from smem z ---
    if (tid < MTILE) {
        const int m = tid;
        unsigned short* arow = (unsigned short*)(sm + A_B) + m * APITCH;
        float s = 0.f;
#pragma unroll
        for (int c = 0; c < CDIM; ++c) {
            float z = zs[c * MTILE + m];
            s = __fadd_rn(s, __fmul_rn(z, z));
            __nv_bfloat16 zh = __float2bfloat16(z);
            __nv_bfloat16 zl = __float2bfloat16(z - __bfloat162float(zh));
            arow[c]      = __bfloat16_as_ushort(zh);
            arow[64 + c] = __bfloat16_as_ushort(zl);
        }
        zzs[m] = s;
    }
    __syncthreads();

    // lane-invariant ldmatrix row components (mapping validated R6)
    const int lrow = (lane & 7) + ((lane >> 3) & 1) * 8;   // row within 16
    const int lkof = (lane >> 4) * 8;                      // k half
    const unsigned a_base =
        smem_base + A_B + (unsigned)((rg * 32 + lrow) * APITCH + lkof) * 2;
    const unsigned b_row = (unsigned)((cg * 16 + lrow) * BPITCH + lkof) * 2;

    float zzr[4];
#pragma unroll
    for (int ri = 0; ri < 4; ++ri)
        zzr[ri] = zzs[rg * 32 + (ri >> 1) * 16 + (ri & 1) * 8 + (lane >> 2)];

    float td1[4], td2[4], td3[4];
    int   ti1[4], ti2[4], ti3[4];
#pragma unroll
    for (int ri = 0; ri < 4; ++ri) {
        td1[ri] = CUDART_INF_F; td2[ri] = CUDART_INF_F; td3[ri] = CUDART_INF_F;
        ti1[ri] = 0; ti2[ri] = 0; ti3[ri] = 0;
    }

    for (int chunk = 0; chunk < NCHUNKS; ++chunk) {
        const int cur = chunk & 1;

        if (chunk < NCHUNKS - 1) {
            const uint4* src =
                (const uint4*)(g_bh + (size_t)(chunk + 1) * CHUNKC * BPITCH);
            unsigned dstb = smem_base + (cur ? B0_B : B1_B);
            unsigned dste = smem_base + (cur ? EES0_B : EES1_B);
#pragma unroll
            for (int i = 0; i < 2; ++i) {
                int idx = tid + i * NTHREADS;
                if (idx < B_CHUNK_U4) cpa16(dstb + idx * 16, src + idx);
            }
            if (tid < CHUNKC) cpa4(dste + tid * 4, &g_ee[(chunk + 1) * CHUNKC + tid]);
            cpa_commit();
            cpa_wait<1>();
        } else {
            cpa_wait<0>();
        }
        __syncthreads();

        const unsigned b_base = smem_base + (cur ? B1_B : B0_B) + b_row;
        const float* ees = (const float*)(sm + (cur ? EES1_B : EES0_B));

        float acc[2][2][4];
#pragma unroll
        for (int rf = 0; rf < 2; ++rf)
#pragma unroll
            for (int j = 0; j < 2; ++j)
#pragma unroll
                for (int r = 0; r < 4; ++r) acc[rf][j][r] = 0.f;

#pragma unroll
        for (int s = 0; s < NKS; ++s) {
            unsigned a0, a1, a2, a3, e0, e1, e2, e3, b0, b1, b2, b3;
            ldsm4(a0, a1, a2, a3, a_base + (unsigned)(s * 16) * 2);
            ldsm4(e0, e1, e2, e3, a_base + (unsigned)(16 * APITCH + s * 16) * 2);
            ldsm4(b0, b1, b2, b3, b_base + (unsigned)((s & 3) * 16) * 2);  // [eh] reused
            mma16816(acc[0][0], a0, a1, a2, a3, b0, b2);
            mma16816(acc[0][1], a0, a1, a2, a3, b1, b3);
            mma16816(acc[1][0], e0, e1, e2, e3, b0, b2);
            mma16816(acc[1][1], e0, e1, e2, e3, b1, b3);
        }

        // --- screen: d = zz + ee - 2*(z.eh), per-thread top-3 per row ---
#pragma unroll
        for (int rf = 0; rf < 2; ++rf) {
#pragma unroll
            for (int j = 0; j < 2; ++j) {
                int e0i = cg * 16 + j * 8 + (lane & 3) * 2;
                int cg0 = chunk * CHUNKC + e0i;
                float ee0 = ees[e0i], ee1 = ees[e0i + 1];
#pragma unroll
                for (int r = 0; r < 4; ++r) {
                    float ee = (r & 1) ? ee1 : ee0;
                    int   cgi = cg0 + (r & 1);
                    int   ri = rf * 2 + (r >> 1);
                    float d  = fmaf(-2.0f, acc[rf][j][r], zzr[ri] + ee);
                    if (d < td1[ri]) {
                        td3[ri] = td2[ri]; ti3[ri] = ti2[ri];
                        td2[ri] = td1[ri]; ti2[ri] = ti1[ri];
                        td1[ri] = d;       ti1[ri] = cgi;
                    } else if (d < td2[ri]) {
                        td3[ri] = td2[ri]; ti3[ri] = ti2[ri];
                        td2[ri] = d;       ti2[ri] = cgi;
                    } else if (d < td3[ri]) {
                        td3[ri] = d;       ti3[ri] = cgi;
                    }
                }
            }
        }
        __syncthreads();
    }

    // --- merge top-3 across the quad (lanes differing in bits 0,1) ---
#pragma unroll
    for (int xm = 1; xm <= 2; xm <<= 1) {
#pragma unroll
        for (int ri = 0; ri < 4; ++ri) {
            float b1d = __shfl_xor_sync(0xffffffffu, td1[ri], xm);
            int   b1i = __shfl_xor_sync(0xffffffffu, ti1[ri], xm);
            float b2d = __shfl_xor_sync(0xffffffffu, td2[ri], xm);
            int   b2i = __shfl_xor_sync(0xffffffffu, ti2[ri], xm);
            float b3d = __shfl_xor_sync(0xffffffffu, td3[ri], xm);
            int   b3i = __shfl_xor_sync(0xffffffffu, ti3[ri], xm);
            float a1d = td1[ri], a2d = td2[ri], a3d = td3[ri];
            int   a1i = ti1[ri], a2i = ti2[ri], a3i = ti3[ri];
            if (better(b1d, b1i, a1d, a1i)) {
                float t; int x;
                t = a1d; a1d = b1d; b1d = t;  x = a1i; a1i = b1i; b1i = x;
                t = a2d; a2d = b2d; b2d = t;  x = a2i; a2i = b2i; b2i = x;
                t = a3d; a3d = b3d; b3d = t;  x = a3i; a3i = b3i; b3i = x;
            }
            if (better(b1d, b1i, a2d, a2i)) {
                bool k = better(a2d, a2i, b2d, b2i);
                a3d = k ? a2d : b2d;  a3i = k ? a2i : b2i;
                a2d = b1d;            a2i = b1i;
            } else if (better(b1d, b1i, a3d, a3i)) {
                a3d = b1d; a3i = b1i;
            }
            td1[ri] = a1d; ti1[ri] = a1i;
            td2[ri] = a2d; ti2[ri] = a2i;
            td3[ri] = a3d; ti3[ri] = a3i;
        }
    }

    // per-quarter top-3 into merge arrays (A image dead)
    float* mgd = (float*)(sm + MGD_B);   // [cg*3 + rank][row]
    int*   mgi = (int*)(sm + MGI_B);
    if ((lane & 3) == 0) {
#pragma unroll
        for (int ri = 0; ri < 4; ++ri) {
            int row = rg * 32 + (ri >> 1) * 16 + (ri & 1) * 8 + (lane >> 2);
            mgd[(cg * 3 + 0) * MTILE + row] = td1[ri];
            mgi[(cg * 3 + 0) * MTILE + row] = ti1[ri];
            mgd[(cg * 3 + 1) * MTILE + row] = td2[ri];
            mgi[(cg * 3 + 1) * MTILE + row] = ti2[ri];
            mgd[(cg * 3 + 2) * MTILE + row] = td3[ri];
            mgi[(cg * 3 + 2) * MTILE + row] = ti3[ri];
        }
    }
    __syncthreads();

    // --- select global top-4 of 12 by screen value (128 threads) ---
    int* cand = (int*)(sm + CAND_B);     // [q][row]
    if (tid < MTILE) {
        const int m = tid;
        float dd[12]; int ii[12];
#pragma unroll
        for (int t = 0; t < 12; ++t) {
            dd[t] = mgd[t * MTILE + m];
            ii[t] = mgi[t * MTILE + m];
        }
#pragma unroll
        for (int k = 0; k < 4; ++k) {
            int bj = k;
#pragma unroll
            for (int j = k + 1; j < 12; ++j)
                if (better(dd[j], ii[j], dd[bj], ii[bj])) bj = j;
            float t = dd[k]; dd[k] = dd[bj]; dd[bj] = t;
            int   x = ii[k]; ii[k] = ii[bj]; ii[bj] = x;
            cand[k * MTILE + m] = ii[k];
        }
    }
    __syncthreads();

    // --- parallel exact fp32 refine: 4 threads per vector, 1 cand each ---
    float* rfnd = (float*)(sm + RFND_B);
    int*   rfni = (int*)(sm + RFNI_B);
    {
        const int q  = tid >> 7;
        const int m2 = tid & 127;
        int ci = cand[q * MTILE + m2];
        float zz2 = zzs[m2];
        const float4* crow = (const float4*)(cb + (size_t)ci * CDIM);
        float a = 0.f;
#pragma unroll
        for (int c4 = 0; c4 < CDIM / 4; ++c4) {
            float4 qv = __ldg(&crow[c4]);
            a = fmaf(zs[(c4 * 4 + 0) * MTILE + m2], qv.x, a);
            a = fmaf(zs[(c4 * 4 + 1) * MTILE + m2], qv.y, a);
            a = fmaf(zs[(c4 * 4 + 2) * MTILE + m2], qv.z, a);
            a = fmaf(zs[(c4 * 4 + 3) * MTILE + m2], qv.w, a);
        }
        rfnd[q * MTILE + m2] = fmaf(-2.0f, a, __fadd_rn(zz2, __ldg(&g_ee[ci])));
        rfni[q * MTILE + m2] = ci;
    }
    __syncthreads();

    // --- final select + outputs (128 threads) ---
    float* stq = (float*)(sm + STQ_B);
    if (tid < MTILE) {
        const int m = tid;
        float bd = rfnd[m]; int bidx = rfni[m];
#pragma unroll
        for (int q = 1; q < 4; ++q) {
            float d = rfnd[q * MTILE + m];
            int   x = rfni[q * MTILE + m];
            if (better(d, x, bd, bidx)) { bd = d; bidx = x; }
        }

        out[Z_ELEMS + (size_t)b * KTOT + k0v + m] = (float)bidx;
        atomicAdd(&g_hist[bidx], 1);

        const float4* crow = (const float4*)(cb + (size_t)bidx * CDIM);
        double lsum = 0.0;
#pragma unroll
        for (int c4 = 0; c4 < CDIM / 4; ++c4) {
            float4 q = __ldg(&crow[c4]);
            float zq[4] = {q.x, q.y, q.z, q.w};
#pragma unroll
            for (int u = 0; u < 4; ++u) {
                int c = c4 * 4 + u;
                float ze = zs[c * MTILE + m];
                float t  = __fsub_rn(zq[u], ze);
                stq[c * MTILE + m] = __fadd_rn(ze, t);
                lsum += (double)__fmul_rn(t, t);
            }
        }
#pragma unroll
        for (int o = 16; o > 0; o >>= 1)
            lsum += __shfl_down_sync(0xffffffffu, lsum, o);
        if ((tid & 31) == 0) sls[tid >> 5] = lsum;
    }
    __syncthreads();
    if (tid == 0)
        g_loss_part[blockIdx.x] = sls[0] + sls[1] + sls[2] + sls[3];

    // --- coalesced z_q_st store ---
    {
        float* ob = out + ((size_t)b * CDIM) * KTOT + k0v;
#pragma unroll
        for (int i = 0; i < 4; ++i) {
            int idx4 = tid + i * NTHREADS;
            int c = idx4 >> 5, v4 = idx4 & 31;
            *(float4*)(ob + (size_t)c * KTOT + v4 * 4) =
                *(const float4*)&stq[c * MTILE + v4 * 4];
        }
    }

    // --- fused finalize: last CTA reduces hist + loss ---
    __threadfence();
    if (tid == 0) {
        int old = atomicAdd(&g_count, 1);
        *flg = (old == NGRID - 1) ? 1 : 0;
    }
    __syncthreads();
    if (*flg) {
        __threadfence();
        float*  red_f = (float*)(sm + RED_B);
        double* red_d = (double*)(sm + RED_B + 2048);
        float ent = 0.f;
#pragma unroll
        for (int i = 0; i < NCODES / NTHREADS; ++i) {
            float p = (float)g_hist[tid + i * NTHREADS] * (1.0f / (float)N_VEC);
            ent += p * logf(p + 1e-10f);
        }
        red_f[tid] = ent;
        red_d[tid] = g_loss_part[tid];
        __syncthreads();
        for (int s = 256; s > 0; s >>= 1) {
            if (tid < s) { red_f[tid] += red_f[tid + s]; red_d[tid] += red_d[tid + s]; }
            __syncthreads();
        }
        if (tid == 0) {
            out[Z_ELEMS + N_VEC]     = (float)(red_d[0] * (1.25 / (double)Z_ELEMS));
            out[Z_ELEMS + N_VEC + 1] = expf(-red_f[0]);
            g_count = 0;   // reset for next graph replay
        }
    }
}

// ---------------------------------------------------------------------------
extern "C" void kernel_launch(void* const* d_in, const int* in_sizes, int n_in,
                              void* d_out, int out_size) {
    const float* z_e = (const float*)d_in[0];
    const float* cb  = (const float*)d_in[1];
    float* out = (float*)d_out;

    cudaFuncSetAttribute(vq_main, cudaFuncAttributeMaxDynamicSharedMemorySize,
                         SMEM_BYTES);

    vq_prep<<<8, 128>>>(cb);
    vq_main<<<NGRID, NTHREADS, SMEM_BYTES>>>(z_e, cb, out);
}

// round 13
// speedup vs baseline: 1.3230x; 1.3230x over previous
#include <cuda_runtime.h>
#include <cuda_bf16.h>
#include <math_constants.h>
#include <math.h>

#define CDIM     64
#define NCODES   1024
#define KTOT     2048
#define BATCH    32
#define N_VEC    (BATCH * KTOT)          // 65536
#define Z_ELEMS  (BATCH * CDIM * KTOT)   // 4194304
#define MTILE    128                     // vectors per CTA
#define NKS      8                       // k16 steps (K=128: A=[zh|zl], B=[eh|eh])
#define CHUNKC   64                      // codes per chunk
#define NCHUNKS  (NCODES / CHUNKC)       // 16
#define NTHREADS 512
#define NGRID    512
#define APITCH   136                     // halves per A row (128 + 8 pad)
#define BPITCH   72                      // halves per B row (64 eh + 8 pad)

// smem layout (bytes)
#define A_B      0                        // A halves 128x136x2 = 34816
#define B0_B     34816                    // B chunk buf0 9216
#define B1_B     44032                    // B chunk buf1 9216
#define ZS_B     53248                    // persistent fp32 z tile 64x128 = 32768
#define EES0_B   86016                    // 64 floats
#define EES1_B   86272                    // 64 floats
#define ZZS_B    86528                    // 128 floats
#define SLS_B    87040                    // 16 doubles
#define FLG_B    87168                    // flag int (+pad)
#define RED_B    87232                    // finalize: 512 f + 512 d = 6144
#define SMEM_BYTES 93376

// post-mainloop reuse inside [0, ZS_B):
#define MGD_B    0                        // float [8][128] = 4096
#define MGI_B    4096                     // int   [8][128] = 4096
#define CAND_B   8192                     // int   [4][128] = 2048
#define RFND_B   10240                    // float [4][128] = 2048
#define RFNI_B   12288                    // int   [4][128] = 2048
#define STQ_B    14336                    // 32768 -> ends 47104 < ZS_B

#define B_CHUNK_U4  576                  // 9216 / 16

__device__ float  g_ee[NCODES];
__device__ int    g_hist[NCODES];
__device__ double g_loss_part[NGRID];
__device__ int    g_count = 0;
__device__ __align__(16) unsigned short g_bh[NCODES * BPITCH];   // [eh] codebook

// ---------------------------------------------------------------------------
__device__ __forceinline__ unsigned smem_u32(const void* p) {
    unsigned a;
    asm("{ .reg .u64 t; cvta.to.shared.u64 t, %1; cvt.u32.u64 %0, t; }"
        : "=r"(a) : "l"(p));
    return a;
}
__device__ __forceinline__ void ldsm4(unsigned& r0, unsigned& r1, unsigned& r2,
                                      unsigned& r3, unsigned addr) {
    asm volatile("ldmatrix.sync.aligned.m8n8.x4.shared.b16 {%0,%1,%2,%3}, [%4];"
                 : "=r"(r0), "=r"(r1), "=r"(r2), "=r"(r3) : "r"(addr));
}
__device__ __forceinline__ void mma16816(float* c, unsigned a0, unsigned a1,
                                         unsigned a2, unsigned a3,
                                         unsigned b0, unsigned b1) {
    asm volatile(
        "mma.sync.aligned.m16n8k16.row.col.f32.bf16.bf16.f32 "
        "{%0,%1,%2,%3}, {%4,%5,%6,%7}, {%8,%9}, {%0,%1,%2,%3};"
        : "+f"(c[0]), "+f"(c[1]), "+f"(c[2]), "+f"(c[3])
        : "r"(a0), "r"(a1), "r"(a2), "r"(a3), "r"(b0), "r"(b1));
}
__device__ __forceinline__ void cpa16(unsigned dst, const void* src) {
    asm volatile("cp.async.cg.shared.global [%0], [%1], 16;"
                 :: "r"(dst), "l"(src));
}
__device__ __forceinline__ void cpa4(unsigned dst, const void* src) {
    asm volatile("cp.async.ca.shared.global [%0], [%1], 4;"
                 :: "r"(dst), "l"(src));
}
__device__ __forceinline__ void cpa_commit() {
    asm volatile("cp.async.commit_group;" ::: "memory");
}
template <int N>
__device__ __forceinline__ void cpa_wait() {
    asm volatile("cp.async.wait_group %0;" :: "n"(N) : "memory");
}
__device__ __forceinline__ bool better(float da, int ia, float db, int ib) {
    return da < db || (da == db && ia < ib);
}

// ---------------------------------------------------------------------------
// prep: code norms (ascending-c), [eh] codebook image, zero hist
// ---------------------------------------------------------------------------
__global__ void vq_prep(const float* __restrict__ cb) {
    int j = blockIdx.x * blockDim.x + threadIdx.x;
    if (j >= NCODES) return;
    const float4* row4 = (const float4*)(cb + j * CDIM);
    float r[CDIM];
#pragma unroll
    for (int q = 0; q < CDIM / 4; ++q) {
        float4 v = __ldg(&row4[q]);
        r[q * 4 + 0] = v.x; r[q * 4 + 1] = v.y;
        r[q * 4 + 2] = v.z; r[q * 4 + 3] = v.w;
    }
    unsigned short* img = g_bh + j * BPITCH;
    float s = 0.f;
#pragma unroll
    for (int c = 0; c < CDIM; ++c) {
        float e = r[c];
        s = __fadd_rn(s, __fmul_rn(e, e));
        img[c] = __bfloat16_as_ushort(__float2bfloat16(e));
    }
#pragma unroll
    for (int c = CDIM; c < BPITCH; ++c) img[c] = 0;
    g_ee[j]   = s;
    g_hist[j] = 0;
}

// ---------------------------------------------------------------------------
// main: HMMA z.eh screen (cheap top-2/thread), refine top-4 of 8 quarter
//       candidates exactly, 2 CTAs/SM, fused finalize. grid=512, block=512.
// ---------------------------------------------------------------------------
__global__ __launch_bounds__(NTHREADS, 2)
void vq_main(const float* __restrict__ z_e, const float* __restrict__ cb,
             float* __restrict__ out) {
    extern __shared__ char sm[];
    float*  zs  = (float*)(sm + ZS_B);      // persistent [c][v] 64x128
    float*  zzs = (float*)(sm + ZZS_B);
    double* sls = (double*)(sm + SLS_B);
    int*    flg = (int*)(sm + FLG_B);
    const unsigned smem_base = smem_u32(sm);

    const int tid  = threadIdx.x;
    const int lane = tid & 31;
    const int w    = tid >> 5;
    const int rg   = w & 3;                 // rows 32rg..32rg+31
    const int cg   = w >> 2;                // codes 16cg..16cg+15
    const int b    = blockIdx.x >> 4;
    const int k0v  = (blockIdx.x & 15) * MTILE;

    // --- kick off B chunk 0 prefetch immediately ---
    {
        const uint4* src = (const uint4*)g_bh;
#pragma unroll
        for (int i = 0; i < 2; ++i) {
            int idx = tid + i * NTHREADS;
            if (idx < B_CHUNK_U4) cpa16(smem_base + B0_B + idx * 16, src + idx);
        }
        if (tid < CHUNKC) cpa4(smem_base + EES0_B + tid * 4, &g_ee[tid]);
        cpa_commit();
    }

    // --- load z tile fp32 (persistent, coalesced float4) ---
    const float* zbase = z_e + ((size_t)b * CDIM) * KTOT + k0v;
#pragma unroll
    for (int i = 0; i < 4; ++i) {
        int idx4 = tid + i * NTHREADS;       // 0..2047
        int c = idx4 >> 5, v4 = idx4 & 31;
        *(float4*)&zs[c * MTILE + v4 * 4] =
            *(const float4*)(zbase + (size_t)c * KTOT + v4 * 4);
    }
    __syncthreads();

    // --- per-vector norm (ascending-c) + A=[zh|zl] image from smem z ---
    if (tid < MTILE) {
        const int m = tid;
        unsigned short* arow = (unsigned short*)(sm + A_B) + m * APITCH;
        float s = 0.f;
#pragma unroll
        for (int c = 0; c < CDIM; ++c) {
            float z = zs[c * MTILE + m];
            s = __fadd_rn(s, __fmul_rn(z, z));
            __nv_bfloat16 zh = __float2bfloat16(z);
            __nv_bfloat16 zl = __float2bfloat16(z - __bfloat162float(zh));
            arow[c]      = __bfloat16_as_ushort(zh);
            arow[64 + c] = __bfloat16_as_ushort(zl);
        }
        zzs[m] = s;
    }
    __syncthreads();

    // lane-invariant ldmatrix row components (mapping validated R6)
    const int lrow = (lane & 7) + ((lane >> 3) & 1) * 8;   // row within 16
    const int lkof = (lane >> 4) * 8;                      // k half
    const unsigned a_base =
        smem_base + A_B + (unsigned)((rg * 32 + lrow) * APITCH + lkof) * 2;
    const unsigned b_row = (unsigned)((cg * 16 + lrow) * BPITCH + lkof) * 2;

    float zzr[4];
#pragma unroll
    for (int ri = 0; ri < 4; ++ri)
        zzr[ri] = zzs[rg * 32 + (ri >> 1) * 16 + (ri & 1) * 8 + (lane >> 2)];

    float td1[4], td2[4];
    int   ti1[4], ti2[4];
#pragma unroll
    for (int ri = 0; ri < 4; ++ri) {
        td1[ri] = CUDART_INF_F; td2[ri] = CUDART_INF_F;
        ti1[ri] = 0; ti2[ri] = 0;
    }

    for (int chunk = 0; chunk < NCHUNKS; ++chunk) {
        const int cur = chunk & 1;

        if (chunk < NCHUNKS - 1) {
            const uint4* src =
                (const uint4*)(g_bh + (size_t)(chunk + 1) * CHUNKC * BPITCH);
            unsigned dstb = smem_base + (cur ? B0_B : B1_B);
            unsigned dste = smem_base + (cur ? EES0_B : EES1_B);
#pragma unroll
            for (int i = 0; i < 2; ++i) {
                int idx = tid + i * NTHREADS;
                if (idx < B_CHUNK_U4) cpa16(dstb + idx * 16, src + idx);
            }
            if (tid < CHUNKC) cpa4(dste + tid * 4, &g_ee[(chunk + 1) * CHUNKC + tid]);
            cpa_commit();
            cpa_wait<1>();
        } else {
            cpa_wait<0>();
        }
        __syncthreads();

        const unsigned b_base = smem_base + (cur ? B1_B : B0_B) + b_row;
        const float* ees = (const float*)(sm + (cur ? EES1_B : EES0_B));

        float acc[2][2][4];
#pragma unroll
        for (int rf = 0; rf < 2; ++rf)
#pragma unroll
            for (int j = 0; j < 2; ++j)
#pragma unroll
                for (int r = 0; r < 4; ++r) acc[rf][j][r] = 0.f;

#pragma unroll
        for (int s = 0; s < NKS; ++s) {
            unsigned a0, a1, a2, a3, e0, e1, e2, e3, b0, b1, b2, b3;
            ldsm4(a0, a1, a2, a3, a_base + (unsigned)(s * 16) * 2);
            ldsm4(e0, e1, e2, e3, a_base + (unsigned)(16 * APITCH + s * 16) * 2);
            ldsm4(b0, b1, b2, b3, b_base + (unsigned)((s & 3) * 16) * 2);  // [eh] reused
            mma16816(acc[0][0], a0, a1, a2, a3, b0, b2);
            mma16816(acc[0][1], a0, a1, a2, a3, b1, b3);
            mma16816(acc[1][0], e0, e1, e2, e3, b0, b2);
            mma16816(acc[1][1], e0, e1, e2, e3, b1, b3);
        }

        // --- screen: d = zz + ee - 2*(z.eh), cheap top-2 per row ---
#pragma unroll
        for (int rf = 0; rf < 2; ++rf) {
#pragma unroll
            for (int j = 0; j < 2; ++j) {
                int e0i = cg * 16 + j * 8 + (lane & 3) * 2;
                int cg0 = chunk * CHUNKC + e0i;
                float ee0 = ees[e0i], ee1 = ees[e0i + 1];
#pragma unroll
                for (int r = 0; r < 4; ++r) {
                    float ee = (r & 1) ? ee1 : ee0;
                    int   cgi = cg0 + (r & 1);
                    int   ri = rf * 2 + (r >> 1);
                    float d  = fmaf(-2.0f, acc[rf][j][r], zzr[ri] + ee);
                    if (d < td1[ri]) {
                        td2[ri] = td1[ri]; ti2[ri] = ti1[ri];
                        td1[ri] = d;       ti1[ri] = cgi;
                    } else if (d < td2[ri]) {
                        td2[ri] = d; ti2[ri] = cgi;
                    }
                }
            }
        }
        __syncthreads();
    }

    // --- merge top-2 across the quad (lanes differing in bits 0,1) ---
#pragma unroll
    for (int xm = 1; xm <= 2; xm <<= 1) {
#pragma unroll
        for (int ri = 0; ri < 4; ++ri) {
            float e1 = __shfl_xor_sync(0xffffffffu, td1[ri], xm);
            int   j1 = __shfl_xor_sync(0xffffffffu, ti1[ri], xm);
            float e2 = __shfl_xor_sync(0xffffffffu, td2[ri], xm);
            int   j2 = __shfl_xor_sync(0xffffffffu, ti2[ri], xm);
            if (better(e1, j1, td1[ri], ti1[ri])) {
                float n2d; int n2i;
                if (better(td1[ri], ti1[ri], e2, j2)) { n2d = td1[ri]; n2i = ti1[ri]; }
                else                                   { n2d = e2;      n2i = j2; }
                td1[ri] = e1; ti1[ri] = j1; td2[ri] = n2d; ti2[ri] = n2i;
            } else {
                if (better(e1, j1, td2[ri], ti2[ri])) { td2[ri] = e1; ti2[ri] = j1; }
            }
        }
    }

    // per-quarter top-2 into merge arrays (A image dead)
    float* mgd = (float*)(sm + MGD_B);   // [cg*2 + rank][row]
    int*   mgi = (int*)(sm + MGI_B);
    if ((lane & 3) == 0) {
#pragma unroll
        for (int ri = 0; ri < 4; ++ri) {
            int row = rg * 32 + (ri >> 1) * 16 + (ri & 1) * 8 + (lane >> 2);
            mgd[(cg * 2 + 0) * MTILE + row] = td1[ri];
            mgi[(cg * 2 + 0) * MTILE + row] = ti1[ri];
            mgd[(cg * 2 + 1) * MTILE + row] = td2[ri];
            mgi[(cg * 2 + 1) * MTILE + row] = ti2[ri];
        }
    }
    __syncthreads();

    // --- select global top-4 of 8 by screen value (128 threads) ---
    int* cand = (int*)(sm + CAND_B);     // [q][row]
    if (tid < MTILE) {
        const int m = tid;
        float dd[8]; int ii[8];
#pragma unroll
        for (int t = 0; t < 8; ++t) {
            dd[t] = mgd[t * MTILE + m];
            ii[t] = mgi[t * MTILE + m];
        }
#pragma unroll
        for (int k = 0; k < 4; ++k) {
            int bj = k;
#pragma unroll
            for (int j = k + 1; j < 8; ++j)
                if (better(dd[j], ii[j], dd[bj], ii[bj])) bj = j;
            float t = dd[k]; dd[k] = dd[bj]; dd[bj] = t;
            int   x = ii[k]; ii[k] = ii[bj]; ii[bj] = x;
            cand[k * MTILE + m] = ii[k];
        }
    }
    __syncthreads();

    // --- parallel exact fp32 refine: 4 threads per vector, 1 cand each ---
    float* rfnd = (float*)(sm + RFND_B);
    int*   rfni = (int*)(sm + RFNI_B);
    {
        const int q  = tid >> 7;
        const int m2 = tid & 127;
        int ci = cand[q * MTILE + m2];
        float zz2 = zzs[m2];
        const float4* crow = (const float4*)(cb + (size_t)ci * CDIM);
        float a = 0.f;
#pragma unroll
        for (int c4 = 0; c4 < CDIM / 4; ++c4) {
            float4 qv = __ldg(&crow[c4]);
            a = fmaf(zs[(c4 * 4 + 0) * MTILE + m2], qv.x, a);
            a = fmaf(zs[(c4 * 4 + 1) * MTILE + m2], qv.y, a);
            a = fmaf(zs[(c4 * 4 + 2) * MTILE + m2], qv.z, a);
            a = fmaf(zs[(c4 * 4 + 3) * MTILE + m2], qv.w, a);
        }
        rfnd[q * MTILE + m2] = fmaf(-2.0f, a, __fadd_rn(zz2, __ldg(&g_ee[ci])));
        rfni[q * MTILE + m2] = ci;
    }
    __syncthreads();

    // --- final select + outputs (128 threads) ---
    float* stq = (float*)(sm + STQ_B);
    if (tid < MTILE) {
        const int m = tid;
        float bd = rfnd[m]; int bidx = rfni[m];
#pragma unroll
        for (int q = 1; q < 4; ++q) {
            float d = rfnd[q * MTILE + m];
            int   x = rfni[q * MTILE + m];
            if (better(d, x, bd, bidx)) { bd = d; bidx = x; }
        }

        out[Z_ELEMS + (size_t)b * KTOT + k0v + m] = (float)bidx;
        atomicAdd(&g_hist[bidx], 1);

        const float4* crow = (const float4*)(cb + (size_t)bidx * CDIM);
        double lsum = 0.0;
#pragma unroll
        for (int c4 = 0; c4 < CDIM / 4; ++c4) {
            float4 q = __ldg(&crow[c4]);
            float zq[4] = {q.x, q.y, q.z, q.w};
#pragma unroll
            for (int u = 0; u < 4; ++u) {
                int c = c4 * 4 + u;
                float ze = zs[c * MTILE + m];
                float t  = __fsub_rn(zq[u], ze);
                stq[c * MTILE + m] = __fadd_rn(ze, t);
                lsum += (double)__fmul_rn(t, t);
            }
        }
#pragma unroll
        for (int o = 16; o > 0; o >>= 1)
            lsum += __shfl_down_sync(0xffffffffu, lsum, o);
        if ((tid & 31) == 0) sls[tid >> 5] = lsum;
    }
    __syncthreads();
    if (tid == 0)
        g_loss_part[blockIdx.x] = sls[0] + sls[1] + sls[2] + sls[3];

    // --- coalesced z_q_st store ---
    {
        float* ob = out + ((size_t)b * CDIM) * KTOT + k0v;
#pragma unroll
        for (int i = 0; i < 4; ++i) {
            int idx4 = tid + i * NTHREADS;
            int c = idx4 >> 5, v4 = idx4 & 31;
            *(float4*)(ob + (size_t)c * KTOT + v4 * 4) =
                *(const float4*)&stq[c * MTILE + v4 * 4];
        }
    }

    // --- fused finalize: last CTA reduces hist + loss ---
    __threadfence();
    if (tid == 0) {
        int old = atomicAdd(&g_count, 1);
        *flg = (old == NGRID - 1) ? 1 : 0;
    }
    __syncthreads();
    if (*flg) {
        __threadfence();
        float*  red_f = (float*)(sm + RED_B);
        double* red_d = (double*)(sm + RED_B + 2048);
        float ent = 0.f;
#pragma unroll
        for (int i = 0; i < NCODES / NTHREADS; ++i) {
            float p = (float)g_hist[tid + i * NTHREADS] * (1.0f / (float)N_VEC);
            ent += p * logf(p + 1e-10f);
        }
        red_f[tid] = ent;
        red_d[tid] = g_loss_part[tid];
        __syncthreads();
        for (int s = 256; s > 0; s >>= 1) {
            if (tid < s) { red_f[tid] += red_f[tid + s]; red_d[tid] += red_d[tid + s]; }
            __syncthreads();
        }
        if (tid == 0) {
            out[Z_ELEMS + N_VEC]     = (float)(red_d[0] * (1.25 / (double)Z_ELEMS));
            out[Z_ELEMS + N_VEC + 1] = expf(-red_f[0]);
            g_count = 0;   // reset for next graph replay
        }
    }
}

// ---------------------------------------------------------------------------
extern "C" void kernel_launch(void* const* d_in, const int* in_sizes, int n_in,
                              void* d_out, int out_size) {
    const float* z_e = (const float*)d_in[0];
    const float* cb  = (const float*)d_in[1];
    float* out = (float*)d_out;

    cudaFuncSetAttribute(vq_main, cudaFuncAttributeMaxDynamicSharedMemorySize,
                         SMEM_BYTES);

    vq_prep<<<8, 128>>>(cb);
    vq_main<<<NGRID, NTHREADS, SMEM_BYTES>>>(z_e, cb, out);
}

// round 14
// speedup vs baseline: 1.7745x; 1.3412x over previous
#include <cuda_runtime.h>
#include <cuda_bf16.h>
#include <math_constants.h>
#include <math.h>

#define CDIM     64
#define NCODES   1024
#define KTOT     2048
#define BATCH    32
#define N_VEC    (BATCH * KTOT)          // 65536
#define Z_ELEMS  (BATCH * CDIM * KTOT)   // 4194304
#define MTILE    128                     // vectors per CTA
#define NKS      4                       // k16 steps (K=64: A=[zh], B=[eh])
#define CHUNKC   64                      // codes per chunk
#define NCHUNKS  (NCODES / CHUNKC)       // 16
#define NTHREADS 512
#define NGRID    512
#define APITCH   72                      // halves per A row (64 zh + 8 pad)
#define BPITCH   72                      // halves per B row (64 eh + 8 pad)

// smem layout (bytes)
#define A_B      0                        // A halves 128x72x2 = 18432
#define B0_B     18432                    // B bufs: 3 x 9216 (triple buffer)
#define ZS_B     46080                    // persistent fp32 z tile 64x128 = 32768
#define EES_B    78848                    // 3 x 64 floats = 768
#define ZZS_B    79616                    // 128 floats
#define SLS_B    80128                    // 16 doubles
#define FLG_B    80256                    // flag int (+pad)
#define RED_B    80320                    // finalize: 512 f + 512 d = 6144
#define SMEM_BYTES 86464

// post-mainloop reuse inside [0, ZS_B):
#define MGP_B    0                        // u32 [8][128] = 4096
#define CAND_B   4096                     // int [4][128] = 2048
#define RFND_B   6144                     // float [4][128] = 2048
#define RFNI_B   8192                     // int [4][128] = 2048
#define STQ_B    10240                    // 32768 -> ends 43008 < ZS_B

#define B_CHUNK_U4  576                  // 9216 / 16

__device__ float  g_ee[NCODES];
__device__ int    g_hist[NCODES];
__device__ double g_loss_part[NGRID];
__device__ int    g_count = 0;
__device__ __align__(16) unsigned short g_bh[NCODES * BPITCH];   // [eh] codebook

// ---------------------------------------------------------------------------
__device__ __forceinline__ unsigned smem_u32(const void* p) {
    unsigned a;
    asm("{ .reg .u64 t; cvta.to.shared.u64 t, %1; cvt.u32.u64 %0, t; }"
        : "=r"(a) : "l"(p));
    return a;
}
__device__ __forceinline__ void ldsm4(unsigned& r0, unsigned& r1, unsigned& r2,
                                      unsigned& r3, unsigned addr) {
    asm volatile("ldmatrix.sync.aligned.m8n8.x4.shared.b16 {%0,%1,%2,%3}, [%4];"
                 : "=r"(r0), "=r"(r1), "=r"(r2), "=r"(r3) : "r"(addr));
}
__device__ __forceinline__ void mma16816(float* c, unsigned a0, unsigned a1,
                                         unsigned a2, unsigned a3,
                                         unsigned b0, unsigned b1) {
    asm volatile(
        "mma.sync.aligned.m16n8k16.row.col.f32.bf16.bf16.f32 "
        "{%0,%1,%2,%3}, {%4,%5,%6,%7}, {%8,%9}, {%0,%1,%2,%3};"
        : "+f"(c[0]), "+f"(c[1]), "+f"(c[2]), "+f"(c[3])
        : "r"(a0), "r"(a1), "r"(a2), "r"(a3), "r"(b0), "r"(b1));
}
__device__ __forceinline__ void cpa16(unsigned dst, const void* src) {
    asm volatile("cp.async.cg.shared.global [%0], [%1], 16;"
                 :: "r"(dst), "l"(src));
}
__device__ __forceinline__ void cpa4(unsigned dst, const void* src) {
    asm volatile("cp.async.ca.shared.global [%0], [%1], 4;"
                 :: "r"(dst), "l"(src));
}
__device__ __forceinline__ void cpa_commit() {
    asm volatile("cp.async.commit_group;" ::: "memory");
}
template <int N>
__device__ __forceinline__ void cpa_wait() {
    asm volatile("cp.async.wait_group %0;" :: "n"(N) : "memory");
}
__device__ __forceinline__ bool better(float da, int ia, float db, int ib) {
    return da < db || (da == db && ia < ib);
}
// ordered-float bits: monotonic unsigned image of a float
__device__ __forceinline__ unsigned ford(float f) {
    unsigned b = __float_as_uint(f);
    return b ^ (0x80000000u | (unsigned)((int)b >> 31));
}

// ---------------------------------------------------------------------------
// prep: code norms (ascending-c), [eh] codebook image, zero hist
// ---------------------------------------------------------------------------
__global__ void vq_prep(const float* __restrict__ cb) {
    int j = blockIdx.x * blockDim.x + threadIdx.x;
    if (j >= NCODES) return;
    const float4* row4 = (const float4*)(cb + j * CDIM);
    float r[CDIM];
#pragma unroll
    for (int q = 0; q < CDIM / 4; ++q) {
        float4 v = __ldg(&row4[q]);
        r[q * 4 + 0] = v.x; r[q * 4 + 1] = v.y;
        r[q * 4 + 2] = v.z; r[q * 4 + 3] = v.w;
    }
    unsigned short* img = g_bh + j * BPITCH;
    float s = 0.f;
#pragma unroll
    for (int c = 0; c < CDIM; ++c) {
        float e = r[c];
        s = __fadd_rn(s, __fmul_rn(e, e));
        img[c] = __bfloat16_as_ushort(__float2bfloat16(e));
    }
#pragma unroll
    for (int c = CDIM; c < BPITCH; ++c) img[c] = 0;
    g_ee[j]   = s;
    g_hist[j] = 0;
}

// ---------------------------------------------------------------------------
// main: K=64 HMMA zh.eh screen, packed-u32 top-2, triple-buffered B,
//       exact fp32 refine of top-4-of-8, fused finalize. grid=512, block=512.
// ---------------------------------------------------------------------------
__global__ __launch_bounds__(NTHREADS, 2)
void vq_main(const float* __restrict__ z_e, const float* __restrict__ cb,
             float* __restrict__ out) {
    extern __shared__ char sm[];
    float*  zs  = (float*)(sm + ZS_B);      // persistent [c][v] 64x128
    float*  zzs = (float*)(sm + ZZS_B);
    double* sls = (double*)(sm + SLS_B);
    int*    flg = (int*)(sm + FLG_B);
    const unsigned smem_base = smem_u32(sm);

    const int tid  = threadIdx.x;
    const int lane = tid & 31;
    const int w    = tid >> 5;
    const int rg   = w & 3;                 // rows 32rg..32rg+31
    const int cg   = w >> 2;                // codes 16cg..16cg+15
    const int b    = blockIdx.x >> 4;
    const int k0v  = (blockIdx.x & 15) * MTILE;

    // --- kick off B chunk 0 prefetch immediately ---
    {
        const uint4* src = (const uint4*)g_bh;
#pragma unroll
        for (int i = 0; i < 2; ++i) {
            int idx = tid + i * NTHREADS;
            if (idx < B_CHUNK_U4) cpa16(smem_base + B0_B + idx * 16, src + idx);
        }
        if (tid < CHUNKC) cpa4(smem_base + EES_B + tid * 4, &g_ee[tid]);
        cpa_commit();
    }

    // --- load z tile fp32 (persistent, coalesced float4) ---
    const float* zbase = z_e + ((size_t)b * CDIM) * KTOT + k0v;
#pragma unroll
    for (int i = 0; i < 4; ++i) {
        int idx4 = tid + i * NTHREADS;       // 0..2047
        int c = idx4 >> 5, v4 = idx4 & 31;
        *(float4*)&zs[c * MTILE + v4 * 4] =
            *(const float4*)(zbase + (size_t)c * KTOT + v4 * 4);
    }
    __syncthreads();

    // --- per-vector norm (ascending-c) + A=[zh] image from smem z ---
    if (tid < MTILE) {
        const int m = tid;
        unsigned short* arow = (unsigned short*)(sm + A_B) + m * APITCH;
        float s = 0.f;
#pragma unroll
        for (int c = 0; c < CDIM; ++c) {
            float z = zs[c * MTILE + m];
            s = __fadd_rn(s, __fmul_rn(z, z));
            arow[c] = __bfloat16_as_ushort(__float2bfloat16(z));
        }
        zzs[m] = s;
    }
    __syncthreads();

    // lane-invariant ldmatrix row components (mapping validated R6)
    const int lrow = (lane & 7) + ((lane >> 3) & 1) * 8;   // row within 16
    const int lkof = (lane >> 4) * 8;                      // k half
    const unsigned a_base =
        smem_base + A_B + (unsigned)((rg * 32 + lrow) * APITCH + lkof) * 2;
    const unsigned b_row = (unsigned)((cg * 16 + lrow) * BPITCH + lkof) * 2;

    unsigned t1[4], t2[4];
#pragma unroll
    for (int ri = 0; ri < 4; ++ri) { t1[ri] = 0xFFFFFFFFu; t2[ri] = 0xFFFFFFFFu; }

    for (int chunk = 0; chunk < NCHUNKS; ++chunk) {
        // --- prefetch chunk+1 into buf (chunk+1)%3 (triple buffer) ---
        if (chunk < NCHUNKS - 1) {
            const uint4* src =
                (const uint4*)(g_bh + (size_t)(chunk + 1) * CHUNKC * BPITCH);
            unsigned dstb = smem_base + B0_B + ((chunk + 1) % 3) * 9216;
            unsigned dste = smem_base + EES_B + ((chunk + 1) % 3) * 256;
#pragma unroll
            for (int i = 0; i < 2; ++i) {
                int idx = tid + i * NTHREADS;
                if (idx < B_CHUNK_U4) cpa16(dstb + idx * 16, src + idx);
            }
            if (tid < CHUNKC) cpa4(dste + tid * 4, &g_ee[(chunk + 1) * CHUNKC + tid]);
            cpa_commit();
            cpa_wait<1>();
        } else {
            cpa_wait<0>();
        }
        __syncthreads();   // buf chunk%3 visible to all warps

        const unsigned b_base = smem_base + B0_B + (chunk % 3) * 9216 + b_row;
        const float* ees = (const float*)(sm + EES_B + (chunk % 3) * 256);

        float acc[2][2][4];
#pragma unroll
        for (int rf = 0; rf < 2; ++rf)
#pragma unroll
            for (int j = 0; j < 2; ++j)
#pragma unroll
                for (int r = 0; r < 4; ++r) acc[rf][j][r] = 0.f;

#pragma unroll
        for (int s = 0; s < NKS; ++s) {
            unsigned a0, a1, a2, a3, e0, e1, e2, e3, b0, b1, b2, b3;
            ldsm4(a0, a1, a2, a3, a_base + (unsigned)(s * 16) * 2);
            ldsm4(e0, e1, e2, e3, a_base + (unsigned)(16 * APITCH + s * 16) * 2);
            ldsm4(b0, b1, b2, b3, b_base + (unsigned)(s * 16) * 2);
            mma16816(acc[0][0], a0, a1, a2, a3, b0, b2);
            mma16816(acc[0][1], a0, a1, a2, a3, b1, b3);
            mma16816(acc[1][0], e0, e1, e2, e3, b0, b2);
            mma16816(acc[1][1], e0, e1, e2, e3, b1, b3);
        }

        // --- screen: d' = ee - 2*(zh.eh)  (zz dropped: row-constant),
        //     packed u32 = ordered(d')[31:10] | code, top-2 min-chains ---
#pragma unroll
        for (int j = 0; j < 2; ++j) {
            int e0i = cg * 16 + j * 8 + (lane & 3) * 2;
            unsigned cg0 = (unsigned)(chunk * CHUNKC + e0i);
            float ee0 = ees[e0i], ee1 = ees[e0i + 1];
#pragma unroll
            for (int rf = 0; rf < 2; ++rf) {
#pragma unroll
                for (int r = 0; r < 4; ++r) {
                    float ee = (r & 1) ? ee1 : ee0;
                    unsigned idx = cg0 + (unsigned)(r & 1);
                    int ri = rf * 2 + (r >> 1);
                    float dp = fmaf(-2.0f, acc[rf][j][r], ee);
                    unsigned pk = (ford(dp) & 0xFFFFFC00u) | idx;
                    if (pk < t1[ri]) { t2[ri] = t1[ri]; t1[ri] = pk; }
                    else if (pk < t2[ri]) t2[ri] = pk;
                }
            }
        }
        // no trailing barrier: triple buffer guarantees overwrite safety
    }

    // --- merge top-2 across the quad (lanes differing in bits 0,1) ---
#pragma unroll
    for (int xm = 1; xm <= 2; xm <<= 1) {
#pragma unroll
        for (int ri = 0; ri < 4; ++ri) {
            unsigned o1 = __shfl_xor_sync(0xffffffffu, t1[ri], xm);
            unsigned o2 = __shfl_xor_sync(0xffffffffu, t2[ri], xm);
            unsigned lo = min(t1[ri], o1);
            unsigned hi = max(t1[ri], o1);
            t2[ri] = min(hi, min(t2[ri], o2));
            t1[ri] = lo;
        }
    }

    __syncthreads();   // mainloop ldsm fully done before A region reuse

    // per-quarter top-2 into merge array [cg*2+rank][row]
    unsigned* mgp = (unsigned*)(sm + MGP_B);
    if ((lane & 3) == 0) {
#pragma unroll
        for (int ri = 0; ri < 4; ++ri) {
            int row = rg * 32 + (ri >> 1) * 16 + (ri & 1) * 8 + (lane >> 2);
            mgp[(cg * 2 + 0) * MTILE + row] = t1[ri];
            mgp[(cg * 2 + 1) * MTILE + row] = t2[ri];
        }
    }
    __syncthreads();

    // --- select global top-4 of 8 packed values (128 threads) ---
    int* cand = (int*)(sm + CAND_B);
    if (tid < MTILE) {
        const int m = tid;
        unsigned pp[8];
#pragma unroll
        for (int t = 0; t < 8; ++t) pp[t] = mgp[t * MTILE + m];
#pragma unroll
        for (int k = 0; k < 4; ++k) {
            int bj = k;
#pragma unroll
            for (int j = k + 1; j < 8; ++j)
                if (pp[j] < pp[bj]) bj = j;
            unsigned t = pp[k]; pp[k] = pp[bj]; pp[bj] = t;
            cand[k * MTILE + m] = (int)(pp[k] & 1023u);
        }
    }
    __syncthreads();

    // --- parallel exact fp32 refine: 4 threads per vector, 1 cand each ---
    float* rfnd = (float*)(sm + RFND_B);
    int*   rfni = (int*)(sm + RFNI_B);
    {
        const int q  = tid >> 7;
        const int m2 = tid & 127;
        int ci = cand[q * MTILE + m2];
        float zz2 = zzs[m2];
        const float4* crow = (const float4*)(cb + (size_t)ci * CDIM);
        float a = 0.f;
#pragma unroll
        for (int c4 = 0; c4 < CDIM / 4; ++c4) {
            float4 qv = __ldg(&crow[c4]);
            a = fmaf(zs[(c4 * 4 + 0) * MTILE + m2], qv.x, a);
            a = fmaf(zs[(c4 * 4 + 1) * MTILE + m2], qv.y, a);
            a = fmaf(zs[(c4 * 4 + 2) * MTILE + m2], qv.z, a);
            a = fmaf(zs[(c4 * 4 + 3) * MTILE + m2], qv.w, a);
        }
        rfnd[q * MTILE + m2] = fmaf(-2.0f, a, __fadd_rn(zz2, __ldg(&g_ee[ci])));
        rfni[q * MTILE + m2] = ci;
    }
    __syncthreads();

    // --- final select + outputs (128 threads) ---
    float* stq = (float*)(sm + STQ_B);
    if (tid < MTILE) {
        const int m = tid;
        float bd = rfnd[m]; int bidx = rfni[m];
#pragma unroll
        for (int q = 1; q < 4; ++q) {
            float d = rfnd[q * MTILE + m];
            int   x = rfni[q * MTILE + m];
            if (better(d, x, bd, bidx)) { bd = d; bidx = x; }
        }

        out[Z_ELEMS + (size_t)b * KTOT + k0v + m] = (float)bidx;
        atomicAdd(&g_hist[bidx], 1);

        const float4* crow = (const float4*)(cb + (size_t)bidx * CDIM);
        double lsum = 0.0;
#pragma unroll
        for (int c4 = 0; c4 < CDIM / 4; ++c4) {
            float4 q = __ldg(&crow[c4]);
            float zq[4] = {q.x, q.y, q.z, q.w};
#pragma unroll
            for (int u = 0; u < 4; ++u) {
                int c = c4 * 4 + u;
                float ze = zs[c * MTILE + m];
                float t  = __fsub_rn(zq[u], ze);
                stq[c * MTILE + m] = __fadd_rn(ze, t);
                lsum += (double)__fmul_rn(t, t);
            }
        }
#pragma unroll
        for (int o = 16; o > 0; o >>= 1)
            lsum += __shfl_down_sync(0xffffffffu, lsum, o);
        if ((tid & 31) == 0) sls[tid >> 5] = lsum;
    }
    __syncthreads();
    if (tid == 0)
        g_loss_part[blockIdx.x] = sls[0] + sls[1] + sls[2] + sls[3];

    // --- coalesced z_q_st store ---
    {
        float* ob = out + ((size_t)b * CDIM) * KTOT + k0v;
#pragma unroll
        for (int i = 0; i < 4; ++i) {
            int idx4 = tid + i * NTHREADS;
            int c = idx4 >> 5, v4 = idx4 & 31;
            *(float4*)(ob + (size_t)c * KTOT + v4 * 4) =
                *(const float4*)&stq[c * MTILE + v4 * 4];
        }
    }

    // --- fused finalize: last CTA reduces hist + loss ---
    __threadfence();
    if (tid == 0) {
        int old = atomicAdd(&g_count, 1);
        *flg = (old == NGRID - 1) ? 1 : 0;
    }
    __syncthreads();
    if (*flg) {
        __threadfence();
        float*  red_f = (float*)(sm + RED_B);
        double* red_d = (double*)(sm + RED_B + 2048);
        float ent = 0.f;
#pragma unroll
        for (int i = 0; i < NCODES / NTHREADS; ++i) {
            float p = (float)g_hist[tid + i * NTHREADS] * (1.0f / (float)N_VEC);
            ent += p * logf(p + 1e-10f);
        }
        red_f[tid] = ent;
        red_d[tid] = g_loss_part[tid];
        __syncthreads();
        for (int s = 256; s > 0; s >>= 1) {
            if (tid < s) { red_f[tid] += red_f[tid + s]; red_d[tid] += red_d[tid + s]; }
            __syncthreads();
        }
        if (tid == 0) {
            out[Z_ELEMS + N_VEC]     = (float)(red_d[0] * (1.25 / (double)Z_ELEMS));
            out[Z_ELEMS + N_VEC + 1] = expf(-red_f[0]);
            g_count = 0;   // reset for next graph replay
        }
    }
}

// ---------------------------------------------------------------------------
extern "C" void kernel_launch(void* const* d_in, const int* in_sizes, int n_in,
                              void* d_out, int out_size) {
    const float* z_e = (const float*)d_in[0];
    const float* cb  = (const float*)d_in[1];
    float* out = (float*)d_out;

    cudaFuncSetAttribute(vq_main, cudaFuncAttributeMaxDynamicSharedMemorySize,
                         SMEM_BYTES);

    vq_prep<<<8, 128>>>(cb);
    vq_main<<<NGRID, NTHREADS, SMEM_BYTES>>>(z_e, cb, out);
}

// round 15
// speedup vs baseline: 2.0307x; 1.1444x over previous
#include <cuda_runtime.h>
#include <cuda_bf16.h>
#include <math_constants.h>
#include <math.h>

#define CDIM     64
#define NCODES   1024
#define KTOT     2048
#define BATCH    32
#define N_VEC    (BATCH * KTOT)          // 65536
#define Z_ELEMS  (BATCH * CDIM * KTOT)   // 4194304
#define MTILE    128                     // vectors per tile
#define NTILES   512
#define NKS      4                       // k16 steps (K=64: A=[zh], B=[eh])
#define CHUNKC   64                      // codes per chunk
#define NCHUNKS  (NCODES / CHUNKC)       // 16
#define NTHREADS 512
#define NGRID    256                     // single wave (<=296); 2 tiles per CTA
#define APITCH   72
#define BPITCH   72

// smem layout (bytes)
#define A_B      0                        // A halves 128x72x2 = 18432
#define B0_B     18432                    // B bufs: 3 x 9216 (triple buffer)
#define ZS_B     46080                    // persistent fp32 z tile 64x128 = 32768
#define EES_B    78848                    // 3 x 64 floats (ee + 0.25)
#define ZZS_B    79616                    // 128 floats
#define SLS_B    80128                    // 16 doubles
#define FLG_B    80256                    // flag int (+pad)
#define RED_B    80320                    // finalize: 512 f + 512 d = 6144
#define SMEM_BYTES 86464

// post-mainloop reuse inside [0, ZS_B):
#define MGP_B    0                        // u32 [8][128] = 4096
#define CAND_B   4096                     // int [4][128] = 2048
#define RFND_B   6144                     // float [4][128] = 2048
#define RFNI_B   8192                     // int [4][128] = 2048
#define STQ_B    10240                    // 32768 -> ends 43008 < ZS_B

#define B_CHUNK_U4  576                  // 9216 / 16

__device__ float  g_ee[NCODES];          // exact norms (refine)
__device__ float  g_eeq[NCODES];         // ee + 0.25 (screen, positivity offset)
__device__ int    g_hist[NCODES];
__device__ double g_loss_part[NGRID];
__device__ int    g_count = 0;
__device__ __align__(16) unsigned short g_bh[NCODES * BPITCH];   // [eh] codebook

// ---------------------------------------------------------------------------
__device__ __forceinline__ unsigned smem_u32(const void* p) {
    unsigned a;
    asm("{ .reg .u64 t; cvta.to.shared.u64 t, %1; cvt.u32.u64 %0, t; }"
        : "=r"(a) : "l"(p));
    return a;
}
__device__ __forceinline__ void ldsm4(unsigned& r0, unsigned& r1, unsigned& r2,
                                      unsigned& r3, unsigned addr) {
    asm volatile("ldmatrix.sync.aligned.m8n8.x4.shared.b16 {%0,%1,%2,%3}, [%4];"
                 : "=r"(r0), "=r"(r1), "=r"(r2), "=r"(r3) : "r"(addr));
}
__device__ __forceinline__ void mma16816(float* c, unsigned a0, unsigned a1,
                                         unsigned a2, unsigned a3,
                                         unsigned b0, unsigned b1) {
    asm volatile(
        "mma.sync.aligned.m16n8k16.row.col.f32.bf16.bf16.f32 "
        "{%0,%1,%2,%3}, {%4,%5,%6,%7}, {%8,%9}, {%0,%1,%2,%3};"
        : "+f"(c[0]), "+f"(c[1]), "+f"(c[2]), "+f"(c[3])
        : "r"(a0), "r"(a1), "r"(a2), "r"(a3), "r"(b0), "r"(b1));
}
__device__ __forceinline__ void cpa16(unsigned dst, const void* src) {
    asm volatile("cp.async.cg.shared.global [%0], [%1], 16;"
                 :: "r"(dst), "l"(src));
}
__device__ __forceinline__ void cpa4(unsigned dst, const void* src) {
    asm volatile("cp.async.ca.shared.global [%0], [%1], 4;"
                 :: "r"(dst), "l"(src));
}
__device__ __forceinline__ void cpa_commit() {
    asm volatile("cp.async.commit_group;" ::: "memory");
}
template <int N>
__device__ __forceinline__ void cpa_wait() {
    asm volatile("cp.async.wait_group %0;" :: "n"(N) : "memory");
}
__device__ __forceinline__ bool better(float da, int ia, float db, int ib) {
    return da < db || (da == db && ia < ib);
}

// ---------------------------------------------------------------------------
// prep: code norms (ascending-c), [eh] codebook image, zero hist
// ---------------------------------------------------------------------------
__global__ void vq_prep(const float* __restrict__ cb) {
    int j = blockIdx.x * blockDim.x + threadIdx.x;
    if (j >= NCODES) return;
    const float4* row4 = (const float4*)(cb + j * CDIM);
    float r[CDIM];
#pragma unroll
    for (int q = 0; q < CDIM / 4; ++q) {
        float4 v = __ldg(&row4[q]);
        r[q * 4 + 0] = v.x; r[q * 4 + 1] = v.y;
        r[q * 4 + 2] = v.z; r[q * 4 + 3] = v.w;
    }
    unsigned short* img = g_bh + j * BPITCH;
    float s = 0.f;
#pragma unroll
    for (int c = 0; c < CDIM; ++c) {
        float e = r[c];
        s = __fadd_rn(s, __fmul_rn(e, e));
        img[c] = __bfloat16_as_ushort(__float2bfloat16(e));
    }
#pragma unroll
    for (int c = CDIM; c < BPITCH; ++c) img[c] = 0;
    g_ee[j]   = s;
    g_eeq[j]  = s + 0.25f;               // positivity offset for screen packing
    g_hist[j] = 0;
}

// ---------------------------------------------------------------------------
// main: persistent 2-tile CTAs, K=64 HMMA screen (positive-packed top-2),
//       triple-buffered B, exact fp32 refine, fused finalize.
// grid=256, block=512.
// ---------------------------------------------------------------------------
__global__ __launch_bounds__(NTHREADS, 2)
void vq_main(const float* __restrict__ z_e, const float* __restrict__ cb,
             float* __restrict__ out) {
    extern __shared__ char sm[];
    float*  zs  = (float*)(sm + ZS_B);
    float*  zzs = (float*)(sm + ZZS_B);
    double* sls = (double*)(sm + SLS_B);
    int*    flg = (int*)(sm + FLG_B);
    const unsigned smem_base = smem_u32(sm);

    const int tid  = threadIdx.x;
    const int lane = tid & 31;
    const int w    = tid >> 5;
    const int rg   = w & 3;
    const int cg   = w >> 2;
    const int lrow = (lane & 7) + ((lane >> 3) & 1) * 8;
    const int lkof = (lane >> 4) * 8;
    const unsigned a_base =
        smem_base + A_B + (unsigned)((rg * 32 + lrow) * APITCH + lkof) * 2;
    const unsigned b_row = (unsigned)((cg * 16 + lrow) * BPITCH + lkof) * 2;

    double loss_acc = 0.0;

    for (int t = 0; t < 2; ++t) {
        const int tile = blockIdx.x * 2 + t;
        const int b    = tile >> 4;
        const int k0v  = (tile & 15) * MTILE;

        // --- prefetch B chunk 0 + screen norms ---
        {
            const uint4* src = (const uint4*)g_bh;
#pragma unroll
            for (int i = 0; i < 2; ++i) {
                int idx = tid + i * NTHREADS;
                if (idx < B_CHUNK_U4) cpa16(smem_base + B0_B + idx * 16, src + idx);
            }
            if (tid < CHUNKC) cpa4(smem_base + EES_B + tid * 4, &g_eeq[tid]);
            cpa_commit();
        }

        // --- load z tile fp32 (persistent, coalesced float4) ---
        const float* zbase = z_e + ((size_t)b * CDIM) * KTOT + k0v;
#pragma unroll
        for (int i = 0; i < 4; ++i) {
            int idx4 = tid + i * NTHREADS;
            int c = idx4 >> 5, v4 = idx4 & 31;
            *(float4*)&zs[c * MTILE + v4 * 4] =
                *(const float4*)(zbase + (size_t)c * KTOT + v4 * 4);
        }
        __syncthreads();

        // --- per-vector norm (ascending-c) + A=[zh] image ---
        if (tid < MTILE) {
            const int m = tid;
            unsigned short* arow = (unsigned short*)(sm + A_B) + m * APITCH;
            float s = 0.f;
#pragma unroll
            for (int c = 0; c < CDIM; ++c) {
                float z = zs[c * MTILE + m];
                s = __fadd_rn(s, __fmul_rn(z, z));
                arow[c] = __bfloat16_as_ushort(__float2bfloat16(z));
            }
            zzs[m] = s;
        }
        __syncthreads();

        unsigned t1[4], t2[4];
#pragma unroll
        for (int ri = 0; ri < 4; ++ri) { t1[ri] = 0xFFFFFFFFu; t2[ri] = 0xFFFFFFFFu; }

        for (int chunk = 0; chunk < NCHUNKS; ++chunk) {
            if (chunk < NCHUNKS - 1) {
                const uint4* src =
                    (const uint4*)(g_bh + (size_t)(chunk + 1) * CHUNKC * BPITCH);
                unsigned dstb = smem_base + B0_B + ((chunk + 1) % 3) * 9216;
                unsigned dste = smem_base + EES_B + ((chunk + 1) % 3) * 256;
#pragma unroll
                for (int i = 0; i < 2; ++i) {
                    int idx = tid + i * NTHREADS;
                    if (idx < B_CHUNK_U4) cpa16(dstb + idx * 16, src + idx);
                }
                if (tid < CHUNKC) cpa4(dste + tid * 4, &g_eeq[(chunk + 1) * CHUNKC + tid]);
                cpa_commit();
                cpa_wait<1>();
            } else {
                cpa_wait<0>();
            }
            __syncthreads();

            const unsigned b_base = smem_base + B0_B + (chunk % 3) * 9216 + b_row;
            const float* ees = (const float*)(sm + EES_B + (chunk % 3) * 256);

            float acc[2][2][4];
#pragma unroll
            for (int rf = 0; rf < 2; ++rf)
#pragma unroll
                for (int j = 0; j < 2; ++j)
#pragma unroll
                    for (int r = 0; r < 4; ++r) acc[rf][j][r] = 0.f;

#pragma unroll
            for (int s = 0; s < NKS; ++s) {
                unsigned a0, a1, a2, a3, e0, e1, e2, e3, b0, b1, b2, b3;
                ldsm4(a0, a1, a2, a3, a_base + (unsigned)(s * 16) * 2);
                ldsm4(e0, e1, e2, e3, a_base + (unsigned)(16 * APITCH + s * 16) * 2);
                ldsm4(b0, b1, b2, b3, b_base + (unsigned)(s * 16) * 2);
                mma16816(acc[0][0], a0, a1, a2, a3, b0, b2);
                mma16816(acc[0][1], a0, a1, a2, a3, b1, b3);
                mma16816(acc[1][0], e0, e1, e2, e3, b0, b2);
                mma16816(acc[1][1], e0, e1, e2, e3, b1, b3);
            }

            // --- screen: d = (ee+0.25) - 2*(zh.eh) > 0 always;
            //     raw bits monotonic -> pk = (bits & ~1023)|idx; branchless top-2
#pragma unroll
            for (int j = 0; j < 2; ++j) {
                int e0i = cg * 16 + j * 8 + (lane & 3) * 2;
                unsigned cg0 = (unsigned)(chunk * CHUNKC + e0i);
                float ee0 = ees[e0i], ee1 = ees[e0i + 1];
#pragma unroll
                for (int rf = 0; rf < 2; ++rf) {
#pragma unroll
                    for (int r = 0; r < 4; ++r) {
                        float ee = (r & 1) ? ee1 : ee0;
                        unsigned idx = cg0 + (unsigned)(r & 1);
                        int ri = rf * 2 + (r >> 1);
                        float dp = fmaf(-2.0f, acc[rf][j][r], ee);
                        unsigned pk = (__float_as_uint(dp) & 0xFFFFFC00u) | idx;
                        unsigned hi = max(pk, t1[ri]);
                        t1[ri] = min(pk, t1[ri]);
                        t2[ri] = min(t2[ri], hi);
                    }
                }
            }
            // no trailing barrier: triple buffer guarantees overwrite safety
        }

        // --- merge top-2 across the quad ---
#pragma unroll
        for (int xm = 1; xm <= 2; xm <<= 1) {
#pragma unroll
            for (int ri = 0; ri < 4; ++ri) {
                unsigned o1 = __shfl_xor_sync(0xffffffffu, t1[ri], xm);
                unsigned o2 = __shfl_xor_sync(0xffffffffu, t2[ri], xm);
                unsigned lo = min(t1[ri], o1);
                unsigned hi = max(t1[ri], o1);
                t2[ri] = min(hi, min(t2[ri], o2));
                t1[ri] = lo;
            }
        }

        __syncthreads();   // mainloop done before A region reuse

        unsigned* mgp = (unsigned*)(sm + MGP_B);
        if ((lane & 3) == 0) {
#pragma unroll
            for (int ri = 0; ri < 4; ++ri) {
                int row = rg * 32 + (ri >> 1) * 16 + (ri & 1) * 8 + (lane >> 2);
                mgp[(cg * 2 + 0) * MTILE + row] = t1[ri];
                mgp[(cg * 2 + 1) * MTILE + row] = t2[ri];
            }
        }
        __syncthreads();

        // --- select global top-4 of 8 packed values ---
        int* cand = (int*)(sm + CAND_B);
        if (tid < MTILE) {
            const int m = tid;
            unsigned pp[8];
#pragma unroll
            for (int q = 0; q < 8; ++q) pp[q] = mgp[q * MTILE + m];
#pragma unroll
            for (int k = 0; k < 4; ++k) {
                int bj = k;
#pragma unroll
                for (int j = k + 1; j < 8; ++j)
                    if (pp[j] < pp[bj]) bj = j;
                unsigned tt = pp[k]; pp[k] = pp[bj]; pp[bj] = tt;
                cand[k * MTILE + m] = (int)(pp[k] & 1023u);
            }
        }
        __syncthreads();

        // --- parallel exact fp32 refine: 4 threads per vector ---
        float* rfnd = (float*)(sm + RFND_B);
        int*   rfni = (int*)(sm + RFNI_B);
        {
            const int q  = tid >> 7;
            const int m2 = tid & 127;
            int ci = cand[q * MTILE + m2];
            float zz2 = zzs[m2];
            const float4* crow = (const float4*)(cb + (size_t)ci * CDIM);
            float a = 0.f;
#pragma unroll
            for (int c4 = 0; c4 < CDIM / 4; ++c4) {
                float4 qv = __ldg(&crow[c4]);
                a = fmaf(zs[(c4 * 4 + 0) * MTILE + m2], qv.x, a);
                a = fmaf(zs[(c4 * 4 + 1) * MTILE + m2], qv.y, a);
                a = fmaf(zs[(c4 * 4 + 2) * MTILE + m2], qv.z, a);
                a = fmaf(zs[(c4 * 4 + 3) * MTILE + m2], qv.w, a);
            }
            rfnd[q * MTILE + m2] = fmaf(-2.0f, a, __fadd_rn(zz2, __ldg(&g_ee[ci])));
            rfni[q * MTILE + m2] = ci;
        }
        __syncthreads();

        // --- final select + outputs ---
        float* stq = (float*)(sm + STQ_B);
        if (tid < MTILE) {
            const int m = tid;
            float bd = rfnd[m]; int bidx = rfni[m];
#pragma unroll
            for (int q = 1; q < 4; ++q) {
                float d = rfnd[q * MTILE + m];
                int   x = rfni[q * MTILE + m];
                if (better(d, x, bd, bidx)) { bd = d; bidx = x; }
            }

            out[Z_ELEMS + (size_t)b * KTOT + k0v + m] = (float)bidx;
            atomicAdd(&g_hist[bidx], 1);

            const float4* crow = (const float4*)(cb + (size_t)bidx * CDIM);
            double lsum = 0.0;
#pragma unroll
            for (int c4 = 0; c4 < CDIM / 4; ++c4) {
                float4 q = __ldg(&crow[c4]);
                float zq[4] = {q.x, q.y, q.z, q.w};
#pragma unroll
                for (int u = 0; u < 4; ++u) {
                    int c = c4 * 4 + u;
                    float ze = zs[c * MTILE + m];
                    float tt = __fsub_rn(zq[u], ze);
                    stq[c * MTILE + m] = __fadd_rn(ze, tt);
                    lsum += (double)__fmul_rn(tt, tt);
                }
            }
#pragma unroll
            for (int o = 16; o > 0; o >>= 1)
                lsum += __shfl_down_sync(0xffffffffu, lsum, o);
            if ((tid & 31) == 0) sls[tid >> 5] = lsum;
        }
        __syncthreads();
        if (tid == 0) loss_acc += sls[0] + sls[1] + sls[2] + sls[3];

        // --- coalesced z_q_st store ---
        {
            float* ob = out + ((size_t)b * CDIM) * KTOT + k0v;
#pragma unroll
            for (int i = 0; i < 4; ++i) {
                int idx4 = tid + i * NTHREADS;
                int c = idx4 >> 5, v4 = idx4 & 31;
                *(float4*)(ob + (size_t)c * KTOT + v4 * 4) =
                    *(const float4*)&stq[c * MTILE + v4 * 4];
            }
        }
        __syncthreads();   // stq consumed before next tile's prefetch reuses it
    }

    if (tid == 0) g_loss_part[blockIdx.x] = loss_acc;

    // --- fused finalize: last CTA reduces hist + loss ---
    __threadfence();
    if (tid == 0) {
        int old = atomicAdd(&g_count, 1);
        *flg = (old == NGRID - 1) ? 1 : 0;
    }
    __syncthreads();
    if (*flg) {
        __threadfence();
        float*  red_f = (float*)(sm + RED_B);
        double* red_d = (double*)(sm + RED_B + 2048);
        float ent = 0.f;
#pragma unroll
        for (int i = 0; i < NCODES / NTHREADS; ++i) {
            float p = (float)g_hist[tid + i * NTHREADS] * (1.0f / (float)N_VEC);
            ent += p * logf(p + 1e-10f);
        }
        red_f[tid] = ent;
        red_d[tid] = (tid < NGRID) ? g_loss_part[tid] : 0.0;
        __syncthreads();
        for (int s = 256; s > 0; s >>= 1) {
            if (tid < s) { red_f[tid] += red_f[tid + s]; red_d[tid] += red_d[tid + s]; }
            __syncthreads();
        }
        if (tid == 0) {
            out[Z_ELEMS + N_VEC]     = (float)(red_d[0] * (1.25 / (double)Z_ELEMS));
            out[Z_ELEMS + N_VEC + 1] = expf(-red_f[0]);
            g_count = 0;   // reset for next graph replay
        }
    }
}

// ---------------------------------------------------------------------------
extern "C" void kernel_launch(void* const* d_in, const int* in_sizes, int n_in,
                              void* d_out, int out_size) {
    const float* z_e = (const float*)d_in[0];
    const float* cb  = (const float*)d_in[1];
    float* out = (float*)d_out;

    cudaFuncSetAttribute(vq_main, cudaFuncAttributeMaxDynamicSharedMemorySize,
                         SMEM_BYTES);

    vq_prep<<<8, 128>>>(cb);
    vq_main<<<NGRID, NTHREADS, SMEM_BYTES>>>(z_e, cb, out);
}

// round 16
// speedup vs baseline: 2.0373x; 1.0032x over previous
#include <cuda_runtime.h>
#include <cuda_bf16.h>
#include <math_constants.h>
#include <math.h>

#define CDIM     64
#define NCODES   1024
#define KTOT     2048
#define BATCH    32
#define N_VEC    (BATCH * KTOT)          // 65536
#define Z_ELEMS  (BATCH * CDIM * KTOT)   // 4194304
#define MTILE    128
#define NTILES   512
#define NKS      4                       // K=64: A=[zh], B=[eh]
#define CHUNKC   64
#define NPAIRS   8                       // 8 pairs of 64-code chunks
#define NTHREADS 512
#define NGRID    256                     // 2 tiles per CTA
#define APITCH   72
#define BPITCH   72

// smem layout (bytes)
#define A_B      0                        // A halves 128x72x2 = 18432
#define B0_B     18432                    // 6 B bufs x 9216 (pair triple-buffer) = 55296
#define EES_B    73728                    // 6 x 256 = 1536
#define ZS2_B    10240                    // z fp32 reload (post-mainloop) 32768 -> 43008
#define STQ_B    43008                    // staging 32768 -> 75776 (B+EES dead)
#define ZZS_B    75776                    // 128 floats
#define SLS_B    76288                    // 16 doubles
#define FLG_B    76416                    // flag int (+pad)
#define RED_B    76480                    // finalize: 512 f + 512 d = 6144
#define SMEM_BYTES 82624

// post-mainloop reuse inside A region [0, 10240):
#define MGP_B    0                        // u32 [8][128] = 4096
#define CAND_B   4096                     // int [4][128] = 2048
#define RFND_B   6144                     // float [4][128] = 2048
#define RFNI_B   8192                     // int [4][128] = 2048

#define PAIR_U4  1152                    // 2 chunks x 576 uint4

__device__ float  g_ee[NCODES];          // exact norms (refine)
__device__ float  g_eeq[NCODES];         // ee + 0.25 (screen positivity offset)
__device__ int    g_hist[NCODES];
__device__ double g_loss_part[NGRID];
__device__ int    g_count = 0;
__device__ __align__(16) unsigned short g_bh[NCODES * BPITCH];   // [eh] codebook

// ---------------------------------------------------------------------------
__device__ __forceinline__ unsigned smem_u32(const void* p) {
    unsigned a;
    asm("{ .reg .u64 t; cvta.to.shared.u64 t, %1; cvt.u32.u64 %0, t; }"
        : "=r"(a) : "l"(p));
    return a;
}
__device__ __forceinline__ void ldsm4(unsigned& r0, unsigned& r1, unsigned& r2,
                                      unsigned& r3, unsigned addr) {
    asm volatile("ldmatrix.sync.aligned.m8n8.x4.shared.b16 {%0,%1,%2,%3}, [%4];"
                 : "=r"(r0), "=r"(r1), "=r"(r2), "=r"(r3) : "r"(addr));
}
__device__ __forceinline__ void mma16816(float* c, unsigned a0, unsigned a1,
                                         unsigned a2, unsigned a3,
                                         unsigned b0, unsigned b1) {
    asm volatile(
        "mma.sync.aligned.m16n8k16.row.col.f32.bf16.bf16.f32 "
        "{%0,%1,%2,%3}, {%4,%5,%6,%7}, {%8,%9}, {%0,%1,%2,%3};"
        : "+f"(c[0]), "+f"(c[1]), "+f"(c[2]), "+f"(c[3])
        : "r"(a0), "r"(a1), "r"(a2), "r"(a3), "r"(b0), "r"(b1));
}
__device__ __forceinline__ void cpa16(unsigned dst, const void* src) {
    asm volatile("cp.async.cg.shared.global [%0], [%1], 16;"
                 :: "r"(dst), "l"(src));
}
__device__ __forceinline__ void cpa4(unsigned dst, const void* src) {
    asm volatile("cp.async.ca.shared.global [%0], [%1], 4;"
                 :: "r"(dst), "l"(src));
}
__device__ __forceinline__ void cpa_commit() {
    asm volatile("cp.async.commit_group;" ::: "memory");
}
template <int N>
__device__ __forceinline__ void cpa_wait() {
    asm volatile("cp.async.wait_group %0;" :: "n"(N) : "memory");
}
__device__ __forceinline__ bool better(float da, int ia, float db, int ib) {
    return da < db || (da == db && ia < ib);
}

// ---------------------------------------------------------------------------
// prep: code norms (ascending-c), [eh] codebook image, zero hist
// ---------------------------------------------------------------------------
__global__ void vq_prep(const float* __restrict__ cb) {
    int j = blockIdx.x * blockDim.x + threadIdx.x;
    if (j >= NCODES) return;
    const float4* row4 = (const float4*)(cb + j * CDIM);
    float r[CDIM];
#pragma unroll
    for (int q = 0; q < CDIM / 4; ++q) {
        float4 v = __ldg(&row4[q]);
        r[q * 4 + 0] = v.x; r[q * 4 + 1] = v.y;
        r[q * 4 + 2] = v.z; r[q * 4 + 3] = v.w;
    }
    unsigned short* img = g_bh + j * BPITCH;
    float s = 0.f;
#pragma unroll
    for (int c = 0; c < CDIM; ++c) {
        float e = r[c];
        s = __fadd_rn(s, __fmul_rn(e, e));
        img[c] = __bfloat16_as_ushort(__float2bfloat16(e));
    }
#pragma unroll
    for (int c = CDIM; c < BPITCH; ++c) img[c] = 0;
    g_ee[j]   = s;
    g_eeq[j]  = s + 0.25f;
    g_hist[j] = 0;
}

// ---------------------------------------------------------------------------
// main: 2-tile persistent CTAs; K=64 HMMA screen with pair-granular chunks
//       (8 barriers), pair triple-buffer; exact fp32 refine (z reloaded via
//       cp.async overlapped with merge). grid=256, block=512.
// ---------------------------------------------------------------------------
__global__ __launch_bounds__(NTHREADS, 2)
void vq_main(const float* __restrict__ z_e, const float* __restrict__ cb,
             float* __restrict__ out) {
    extern __shared__ char sm[];
    float*  zzs = (float*)(sm + ZZS_B);
    double* sls = (double*)(sm + SLS_B);
    int*    flg = (int*)(sm + FLG_B);
    const unsigned smem_base = smem_u32(sm);

    const int tid  = threadIdx.x;
    const int lane = tid & 31;
    const int w    = tid >> 5;
    const int rg   = w & 3;
    const int cg   = w >> 2;
    const int lrow = (lane & 7) + ((lane >> 3) & 1) * 8;
    const int lkof = (lane >> 4) * 8;
    const unsigned a_base =
        smem_base + A_B + (unsigned)((rg * 32 + lrow) * APITCH + lkof) * 2;
    const unsigned b_row = (unsigned)((cg * 16 + lrow) * BPITCH + lkof) * 2;

    double loss_acc = 0.0;

    for (int t = 0; t < 2; ++t) {
        const int tile = blockIdx.x * 2 + t;
        const int b    = tile >> 4;
        const int k0v  = (tile & 15) * MTILE;
        const float* zbase = z_e + ((size_t)b * CDIM) * KTOT + k0v;

        // --- prefetch B pair 0 (chunks 0,1) into slot 0 ---
        {
            const uint4* src = (const uint4*)g_bh;
#pragma unroll
            for (int i = 0; i < 3; ++i) {
                int idx = tid + i * NTHREADS;
                if (idx < PAIR_U4) cpa16(smem_base + B0_B + idx * 16, src + idx);
            }
            if (tid < 128) cpa4(smem_base + EES_B + tid * 4, &g_eeq[tid]);
            cpa_commit();
        }

        // --- per-vector norm (ascending-c) + A=[zh] image from gmem ---
        if (tid < MTILE) {
            const int m = tid;
            unsigned short* arow = (unsigned short*)(sm + A_B) + m * APITCH;
            float s = 0.f;
#pragma unroll
            for (int c = 0; c < CDIM; ++c) {
                float z = __ldg(zbase + (size_t)c * KTOT + m);   // coalesced over m
                s = __fadd_rn(s, __fmul_rn(z, z));
                arow[c] = __bfloat16_as_ushort(__float2bfloat16(z));
            }
            zzs[m] = s;
        }
        __syncthreads();

        unsigned t1[4], t2[4];
#pragma unroll
        for (int ri = 0; ri < 4; ++ri) { t1[ri] = 0xFFFFFFFFu; t2[ri] = 0xFFFFFFFFu; }

        for (int p = 0; p < NPAIRS; ++p) {
            // prefetch pair p+1 into slot (p+1)%3 (pair triple-buffer)
            if (p < NPAIRS - 1) {
                const uint4* src =
                    (const uint4*)(g_bh + (size_t)(p + 1) * 2 * CHUNKC * BPITCH);
                unsigned dstb = smem_base + B0_B + ((p + 1) % 3) * 18432;
                unsigned dste = smem_base + EES_B + ((p + 1) % 3) * 512;
#pragma unroll
                for (int i = 0; i < 3; ++i) {
                    int idx = tid + i * NTHREADS;
                    if (idx < PAIR_U4) cpa16(dstb + idx * 16, src + idx);
                }
                if (tid < 128) cpa4(dste + tid * 4, &g_eeq[(p + 1) * 128 + tid]);
                cpa_commit();
                cpa_wait<1>();
            } else {
                cpa_wait<0>();
            }
            __syncthreads();   // pair p visible to all warps

#pragma unroll
            for (int cc = 0; cc < 2; ++cc) {
                const int chunk = p * 2 + cc;
                const unsigned b_base =
                    smem_base + B0_B + (p % 3) * 18432 + cc * 9216 + b_row;
                const float* ees =
                    (const float*)(sm + EES_B + (p % 3) * 512 + cc * 256);

                float acc[2][2][4];
#pragma unroll
                for (int rf = 0; rf < 2; ++rf)
#pragma unroll
                    for (int j = 0; j < 2; ++j)
#pragma unroll
                        for (int r = 0; r < 4; ++r) acc[rf][j][r] = 0.f;

#pragma unroll
                for (int s = 0; s < NKS; ++s) {
                    unsigned a0, a1, a2, a3, e0, e1, e2, e3, b0, b1, b2, b3;
                    ldsm4(a0, a1, a2, a3, a_base + (unsigned)(s * 16) * 2);
                    ldsm4(e0, e1, e2, e3, a_base + (unsigned)(16 * APITCH + s * 16) * 2);
                    ldsm4(b0, b1, b2, b3, b_base + (unsigned)(s * 16) * 2);
                    mma16816(acc[0][0], a0, a1, a2, a3, b0, b2);
                    mma16816(acc[0][1], a0, a1, a2, a3, b1, b3);
                    mma16816(acc[1][0], e0, e1, e2, e3, b0, b2);
                    mma16816(acc[1][1], e0, e1, e2, e3, b1, b3);
                }

                // screen: d = (ee+0.25) - 2*(zh.eh) > 0; raw-bit packed top-2
#pragma unroll
                for (int j = 0; j < 2; ++j) {
                    int e0i = cg * 16 + j * 8 + (lane & 3) * 2;
                    unsigned cg0 = (unsigned)(chunk * CHUNKC + e0i);
                    float ee0 = ees[e0i], ee1 = ees[e0i + 1];
#pragma unroll
                    for (int rf = 0; rf < 2; ++rf) {
#pragma unroll
                        for (int r = 0; r < 4; ++r) {
                            float ee = (r & 1) ? ee1 : ee0;
                            unsigned idx = cg0 + (unsigned)(r & 1);
                            int ri = rf * 2 + (r >> 1);
                            float dp = fmaf(-2.0f, acc[rf][j][r], ee);
                            unsigned pk = (__float_as_uint(dp) & 0xFFFFFC00u) | idx;
                            unsigned hi = max(pk, t1[ri]);
                            t1[ri] = min(pk, t1[ri]);
                            t2[ri] = min(t2[ri], hi);
                        }
                    }
                }
            }
            // no trailing barrier: pair triple-buffer guarantees safety
        }

        // --- merge top-2 across the quad ---
#pragma unroll
        for (int xm = 1; xm <= 2; xm <<= 1) {
#pragma unroll
            for (int ri = 0; ri < 4; ++ri) {
                unsigned o1 = __shfl_xor_sync(0xffffffffu, t1[ri], xm);
                unsigned o2 = __shfl_xor_sync(0xffffffffu, t2[ri], xm);
                unsigned lo = min(t1[ri], o1);
                unsigned hi = max(t1[ri], o1);
                t2[ri] = min(hi, min(t2[ri], o2));
                t1[ri] = lo;
            }
        }

        __syncthreads();   // mainloop done: A + B regions reusable

        // --- kick off z fp32 reload into ZS2 (overlap with merge/select) ---
        float* zs2 = (float*)(sm + ZS2_B);
#pragma unroll
        for (int i = 0; i < 4; ++i) {
            int idx4 = tid + i * NTHREADS;
            int c = idx4 >> 5, v4 = idx4 & 31;
            cpa16(smem_base + ZS2_B + (unsigned)(c * MTILE + v4 * 4) * 4,
                  zbase + (size_t)c * KTOT + v4 * 4);
        }
        cpa_commit();

        unsigned* mgp = (unsigned*)(sm + MGP_B);
        if ((lane & 3) == 0) {
#pragma unroll
            for (int ri = 0; ri < 4; ++ri) {
                int row = rg * 32 + (ri >> 1) * 16 + (ri & 1) * 8 + (lane >> 2);
                mgp[(cg * 2 + 0) * MTILE + row] = t1[ri];
                mgp[(cg * 2 + 1) * MTILE + row] = t2[ri];
            }
        }
        __syncthreads();

        // --- select global top-4 of 8 packed values ---
        int* cand = (int*)(sm + CAND_B);
        if (tid < MTILE) {
            const int m = tid;
            unsigned pp[8];
#pragma unroll
            for (int q = 0; q < 8; ++q) pp[q] = mgp[q * MTILE + m];
#pragma unroll
            for (int k = 0; k < 4; ++k) {
                int bj = k;
#pragma unroll
                for (int j = k + 1; j < 8; ++j)
                    if (pp[j] < pp[bj]) bj = j;
                unsigned tt = pp[k]; pp[k] = pp[bj]; pp[bj] = tt;
                cand[k * MTILE + m] = (int)(pp[k] & 1023u);
            }
        }
        cpa_wait<0>();     // own z copies done
        __syncthreads();   // cand + zs2 visible to all

        // --- parallel exact fp32 refine: 4 threads per vector ---
        float* rfnd = (float*)(sm + RFND_B);
        int*   rfni = (int*)(sm + RFNI_B);
        {
            const int q  = tid >> 7;
            const int m2 = tid & 127;
            int ci = cand[q * MTILE + m2];
            float zz2 = zzs[m2];
            const float4* crow = (const float4*)(cb + (size_t)ci * CDIM);
            float a = 0.f;
#pragma unroll
            for (int c4 = 0; c4 < CDIM / 4; ++c4) {
                float4 qv = __ldg(&crow[c4]);
                a = fmaf(zs2[(c4 * 4 + 0) * MTILE + m2], qv.x, a);
                a = fmaf(zs2[(c4 * 4 + 1) * MTILE + m2], qv.y, a);
                a = fmaf(zs2[(c4 * 4 + 2) * MTILE + m2], qv.z, a);
                a = fmaf(zs2[(c4 * 4 + 3) * MTILE + m2], qv.w, a);
            }
            rfnd[q * MTILE + m2] = fmaf(-2.0f, a, __fadd_rn(zz2, __ldg(&g_ee[ci])));
            rfni[q * MTILE + m2] = ci;
        }
        __syncthreads();

        // --- final select + outputs ---
        float* stq = (float*)(sm + STQ_B);
        if (tid < MTILE) {
            const int m = tid;
            float bd = rfnd[m]; int bidx = rfni[m];
#pragma unroll
            for (int q = 1; q < 4; ++q) {
                float d = rfnd[q * MTILE + m];
                int   x = rfni[q * MTILE + m];
                if (better(d, x, bd, bidx)) { bd = d; bidx = x; }
            }

            out[Z_ELEMS + (size_t)b * KTOT + k0v + m] = (float)bidx;
            atomicAdd(&g_hist[bidx], 1);

            const float4* crow = (const float4*)(cb + (size_t)bidx * CDIM);
            double lsum = 0.0;
#pragma unroll
            for (int c4 = 0; c4 < CDIM / 4; ++c4) {
                float4 q = __ldg(&crow[c4]);
                float zq[4] = {q.x, q.y, q.z, q.w};
#pragma unroll
                for (int u = 0; u < 4; ++u) {
                    int c = c4 * 4 + u;
                    float ze = zs2[c * MTILE + m];
                    float tt = __fsub_rn(zq[u], ze);
                    stq[c * MTILE + m] = __fadd_rn(ze, tt);
                    lsum += (double)__fmul_rn(tt, tt);
                }
            }
#pragma unroll
            for (int o = 16; o > 0; o >>= 1)
                lsum += __shfl_down_sync(0xffffffffu, lsum, o);
            if ((tid & 31) == 0) sls[tid >> 5] = lsum;
        }
        __syncthreads();
        if (tid == 0) loss_acc += sls[0] + sls[1] + sls[2] + sls[3];

        // --- coalesced z_q_st store ---
        {
            float* ob = out + ((size_t)b * CDIM) * KTOT + k0v;
#pragma unroll
            for (int i = 0; i < 4; ++i) {
                int idx4 = tid + i * NTHREADS;
                int c = idx4 >> 5, v4 = idx4 & 31;
                *(float4*)(ob + (size_t)c * KTOT + v4 * 4) =
                    *(const float4*)&stq[c * MTILE + v4 * 4];
            }
        }
        __syncthreads();   // all regions consumed before next tile reuses them
    }

    if (tid == 0) g_loss_part[blockIdx.x] = loss_acc;

    // --- fused finalize: last CTA reduces hist + loss ---
    __threadfence();
    if (tid == 0) {
        int old = atomicAdd(&g_count, 1);
        *flg = (old == NGRID - 1) ? 1 : 0;
    }
    __syncthreads();
    if (*flg) {
        __threadfence();
        float*  red_f = (float*)(sm + RED_B);
        double* red_d = (double*)(sm + RED_B + 2048);
        float ent = 0.f;
#pragma unroll
        for (int i = 0; i < NCODES / NTHREADS; ++i) {
            float p = (float)g_hist[tid + i * NTHREADS] * (1.0f / (float)N_VEC);
            ent += p * logf(p + 1e-10f);
        }
        red_f[tid] = ent;
        red_d[tid] = (tid < NGRID) ? g_loss_part[tid] : 0.0;
        __syncthreads();
        for (int s = 256; s > 0; s >>= 1) {
            if (tid < s) { red_f[tid] += red_f[tid + s]; red_d[tid] += red_d[tid + s]; }
            __syncthreads();
        }
        if (tid == 0) {
            out[Z_ELEMS + N_VEC]     = (float)(red_d[0] * (1.25 / (double)Z_ELEMS));
            out[Z_ELEMS + N_VEC + 1] = expf(-red_f[0]);
            g_count = 0;   // reset for next graph replay
        }
    }
}

// ---------------------------------------------------------------------------
extern "C" void kernel_launch(void* const* d_in, const int* in_sizes, int n_in,
                              void* d_out, int out_size) {
    const float* z_e = (const float*)d_in[0];
    const float* cb  = (const float*)d_in[1];
    float* out = (float*)d_out;

    cudaFuncSetAttribute(vq_main, cudaFuncAttributeMaxDynamicSharedMemorySize,
                         SMEM_BYTES);

    vq_prep<<<8, 128>>>(cb);
    vq_main<<<NGRID, NTHREADS, SMEM_BYTES>>>(z_e, cb, out);
}